// round 3
// baseline (speedup 1.0000x reference)
#include <cuda_runtime.h>
#include <cuda_bf16.h>

#define BB 4
#define PP 2048
#define NROWS (BB*PP)

// ---------------- scratch (device globals; no allocation) ----------------
__device__ float g_combined[NROWS*32];   // raw combined features (31 used)
__device__ float g_encpsi [NROWS*32];    // psi MLP output (masked)
__device__ float g_cum    [NROWS*32];    // cumsum of encpsi along P
__device__ float g_enc    [NROWS*32];    // phi MLP output (masked)
__device__ float g_preattn[BB*4*PP];     // (b,h,p) layout
__device__ float g_w      [BB*4*PP];     // exp(a - M)
__device__ float g_r      [BB*4*PP];     // 1 / prefix-sum of w
__device__ float g_agg2   [NROWS*128];   // out5 reshaped (b,p,h*32+d)

// ---------------- helpers ----------------
__device__ __forceinline__ float block_excl_from_tot(float tot, int tid, float* ws8)
{
    // inclusive warp scan of per-thread totals, then cross-warp via smem.
    float x = tot;
#pragma unroll
    for (int o = 1; o < 32; o <<= 1) {
        float y = __shfl_up_sync(0xffffffffu, x, o);
        if ((tid & 31) >= o) x += y;
    }
    if ((tid & 31) == 31) ws8[tid >> 5] = x;
    __syncthreads();
    float carry = 0.f;
    int w = tid >> 5;
    for (int i = 0; i < w; i++) carry += ws8[i];
    return carry + x - tot;   // exclusive prefix for this thread's chunk
}

// ---------------- K1: combined features + psi MLP ----------------
__global__ __launch_bounds__(256) void k1_psi(
    const float* __restrict__ times, const float* __restrict__ values,
    const int* __restrict__ meas, const float* __restrict__ mask,
    const float* __restrict__ w1, const float* __restrict__ b1,
    const float* __restrict__ w2, const float* __restrict__ b2)
{
    __shared__ float sw1[31*32], sb1[32], sw2[32*32], sb2[32];
    __shared__ float xb[8][32], hb[8][32];
    int tid = threadIdx.x;
    for (int i = tid; i < 31*32; i += 256) sw1[i] = w1[i];
    for (int i = tid; i < 32*32; i += 256) sw2[i] = w2[i];
    if (tid < 32) { sb1[tid] = b1[tid]; sb2[tid] = b2[tid]; }
    __syncthreads();

    int warp = tid >> 5, lane = tid & 31;
    int row  = blockIdx.x * 8 + warp;
    float m = mask[row];

    float c;
    if (lane < 8) {
        const float pv[8] = {1.f,1.f,10.f,10.f,100.f,100.f,1000.f,1000.f};
        float r = times[row] / pv[lane];
        c = ((lane & 1) == 0) ? sinf(r) : cosf(r);
    } else if (lane == 8) {
        c = values[row];
    } else if (lane <= 30) {
        c = (meas[row] == lane - 8) ? 1.f : 0.f;
    } else c = 0.f;

    g_combined[row*32 + lane] = c;
    xb[warp][lane] = c * m;
    __syncwarp();

    float acc = sb1[lane];
#pragma unroll
    for (int i = 0; i < 31; i++) acc = fmaf(xb[warp][i], sw1[i*32 + lane], acc);
    hb[warp][lane] = fmaxf(acc, 0.f) * m;
    __syncwarp();

    acc = sb2[lane];
#pragma unroll
    for (int i = 0; i < 32; i++) acc = fmaf(hb[warp][i], sw2[i*32 + lane], acc);
    g_encpsi[row*32 + lane] = fmaxf(acc, 0.f) * m;
}

// ---------------- K2: cumsum of encpsi along P (one block per (b,d) lane) ----------------
__global__ __launch_bounds__(256) void k2_cumsum()
{
    __shared__ float ws8[8];
    int id = blockIdx.x;              // 0..127
    int b = id >> 5, d = id & 31;
    const float* in = g_encpsi + b*(PP*32) + d;
    float* out = g_cum + b*(PP*32) + d;
    int t = threadIdx.x, p0 = t * 8;

    float v[8];
#pragma unroll
    for (int i = 0; i < 8; i++) v[i] = in[(p0 + i)*32];
#pragma unroll
    for (int i = 1; i < 8; i++) v[i] += v[i-1];
    float excl = block_excl_from_tot(v[7], t, ws8);
#pragma unroll
    for (int i = 0; i < 8; i++) out[(p0 + i)*32] = v[i] + excl;
}

// ---------------- K3: agg (arho), preattn (folded W_k@W_q), phi MLP ----------------
__global__ __launch_bounds__(256) void k3_mid(
    const float* __restrict__ mask,
    const float* __restrict__ arho_w, const float* __restrict__ arho_b,
    const float* __restrict__ W_k,    const float* __restrict__ W_q,
    const float* __restrict__ pw1, const float* __restrict__ pb1,
    const float* __restrict__ pw2, const float* __restrict__ pb2)
{
    __shared__ float sar[32*32], sarb[32];
    __shared__ float sWkq[4*63];
    __shared__ float sw1[31*32], sb1[32], sw2[32*32], sb2[32];
    __shared__ float c2[8][64], hb[8][32], xb[8][32];
    int tid = threadIdx.x;
    for (int i = tid; i < 1024; i += 256) { sar[i] = arho_w[i]; sw2[i] = pw2[i]; }
    for (int i = tid; i < 992;  i += 256) sw1[i] = pw1[i];
    if (tid < 32) { sarb[tid] = arho_b[tid]; sb1[tid] = pb1[tid]; sb2[tid] = pb2[tid]; }
    // fold W_k @ W_q per head: Wkq[h][i] = sum_d W_k[i, d*4+h] * W_q[h, d]
    for (int j = tid; j < 252; j += 256) {
        int h = j / 63, i = j % 63;
        float a = 0.f;
#pragma unroll
        for (int dd = 0; dd < 16; dd++)
            a = fmaf(W_k[i*64 + dd*4 + h], W_q[h*16 + dd], a);
        sWkq[h*63 + i] = a;
    }
    __syncthreads();

    int warp = tid >> 5, lane = tid & 31;
    int row = blockIdx.x * 8 + warp;
    int b = row >> 11, p = row & 2047;
    float m = mask[row];

    float c = g_combined[row*32 + lane];
    c2[warp][lane] = c;                       // comb2[0..31) (idx31 overwritten below)
    xb[warp][lane] = (lane < 31) ? c * m : 0.f;
    hb[warp][lane] = g_cum[row*32 + lane] / (float)(p + 1) * m;  // agg input
    __syncwarp();

    float acc = sarb[lane];
#pragma unroll
    for (int i = 0; i < 32; i++) acc = fmaf(hb[warp][i], sar[i*32 + lane], acc);
    c2[warp][31 + lane] = acc * m;            // comb2[31..63)
    __syncwarp();

    // preattn: 8 lanes per head, strided partial dot then xor reduce
    int h = lane >> 3, ls = lane & 7;
    float pa = 0.f;
    for (int i = ls; i < 63; i += 8) pa = fmaf(c2[warp][i], sWkq[h*63 + i], pa);
    pa += __shfl_xor_sync(0xffffffffu, pa, 1);
    pa += __shfl_xor_sync(0xffffffffu, pa, 2);
    pa += __shfl_xor_sync(0xffffffffu, pa, 4);
    if (ls == 0) g_preattn[(b*4 + h)*PP + p] = pa * 0.25f * m * m;

    // phi MLP on combined*m
    acc = sb1[lane];
#pragma unroll
    for (int i = 0; i < 31; i++) acc = fmaf(xb[warp][i], sw1[i*32 + lane], acc);
    float h1 = fmaxf(acc, 0.f) * m;
    __syncwarp();                // all lanes done reading hb (arho stage)
    hb[warp][lane] = h1;
    __syncwarp();
    acc = sb2[lane];
#pragma unroll
    for (int i = 0; i < 32; i++) acc = fmaf(hb[warp][i], sw2[i*32 + lane], acc);
    g_enc[row*32 + lane] = fmaxf(acc, 0.f) * m;
}

// ---------------- K4: per-(b,h) max, w = exp(a - M), denominator scan, reciprocal ----------------
__global__ __launch_bounds__(256) void k4_den()
{
    __shared__ float wm[8], Ms;
    __shared__ float ws8[8];
    int bh = blockIdx.x;            // 0..15
    const float* a = g_preattn + bh*PP;
    int t = threadIdx.x, lane = t & 31, warp = t >> 5, p0 = t * 8;

    float v[8];
#pragma unroll
    for (int i = 0; i < 8; i++) v[i] = a[p0 + i];
    float mx = v[0];
#pragma unroll
    for (int i = 1; i < 8; i++) mx = fmaxf(mx, v[i]);
#pragma unroll
    for (int o = 16; o > 0; o >>= 1) mx = fmaxf(mx, __shfl_xor_sync(0xffffffffu, mx, o));
    if (lane == 0) wm[warp] = mx;
    __syncthreads();
    if (t == 0) {
        float M = wm[0];
        for (int i = 1; i < 8; i++) M = fmaxf(M, wm[i]);
        Ms = M;
    }
    __syncthreads();
    float M = Ms;

#pragma unroll
    for (int i = 0; i < 8; i++) v[i] = expf(v[i] - M);
    float* w = g_w + bh*PP;
#pragma unroll
    for (int i = 0; i < 8; i++) w[p0 + i] = v[i];

#pragma unroll
    for (int i = 1; i < 8; i++) v[i] += v[i-1];
    float excl = block_excl_from_tot(v[7], t, ws8);
    float* r = g_r + bh*PP;
#pragma unroll
    for (int i = 0; i < 8; i++) r[p0 + i] = 1.0f / (v[i] + excl);
}

// ---------------- K5: numerator scans -> agg2 (one block per (b,h,d) lane) ----------------
__global__ __launch_bounds__(256) void k5_num(const float* __restrict__ mask)
{
    __shared__ float ws8[8];
    int id = blockIdx.x;            // 0..511
    int b = id >> 7, rem = id & 127, h = rem >> 5, d = rem & 31;
    const float* w  = g_w + (b*4 + h)*PP;
    const float* r  = g_r + (b*4 + h)*PP;
    const float* e  = g_enc + b*PP*32 + d;
    const float* mk = mask + b*PP;
    float* o = g_agg2 + b*PP*128 + h*32 + d;
    int t = threadIdx.x, p0 = t * 8;

    float v[8];
#pragma unroll
    for (int i = 0; i < 8; i++) v[i] = w[p0 + i] * e[(p0 + i)*32];
#pragma unroll
    for (int i = 1; i < 8; i++) v[i] += v[i-1];
    float excl = block_excl_from_tot(v[7], t, ws8);
#pragma unroll
    for (int i = 0; i < 8; i++)
        o[(p0 + i)*128] = (v[i] + excl) * r[p0 + i] * mk[p0 + i];
}

// ---------------- K6: rho MLP 128 -> 64 -> 64 ----------------
__global__ __launch_bounds__(256) void k6_rho(
    const float* __restrict__ mask,
    const float* __restrict__ w1, const float* __restrict__ b1,
    const float* __restrict__ w2, const float* __restrict__ b2,
    float* __restrict__ out)
{
    __shared__ float sw1[128*64];    // 32 KB
    __shared__ float sb1[64], sb2[64];
    __shared__ float xb[8][128], hb[8][64];
    int tid = threadIdx.x;
    for (int i = tid; i < 128*64; i += 256) sw1[i] = w1[i];
    if (tid < 64) { sb1[tid] = b1[tid]; sb2[tid] = b2[tid]; }
    __syncthreads();

    int warp = tid >> 5, lane = tid & 31;
    int row = blockIdx.x * 8 + warp;
    float m = mask[row];

    for (int j = lane; j < 128; j += 32) xb[warp][j] = g_agg2[row*128 + j] * m;
    __syncwarp();

    float a0 = sb1[lane], a1 = sb1[lane + 32];
#pragma unroll 8
    for (int i = 0; i < 128; i++) {
        float x = xb[warp][i];
        a0 = fmaf(x, sw1[i*64 + lane], a0);
        a1 = fmaf(x, sw1[i*64 + lane + 32], a1);
    }
    hb[warp][lane]      = fmaxf(a0, 0.f) * m;
    hb[warp][lane + 32] = fmaxf(a1, 0.f) * m;
    __syncwarp();

    a0 = sb2[lane]; a1 = sb2[lane + 32];
#pragma unroll 8
    for (int i = 0; i < 64; i++) {
        float x = hb[warp][i];
        a0 = fmaf(x, __ldg(&w2[i*64 + lane]), a0);
        a1 = fmaf(x, __ldg(&w2[i*64 + lane + 32]), a1);
    }
    out[row*64 + lane]      = fmaxf(a0, 0.f) * m;
    out[row*64 + lane + 32] = fmaxf(a1, 0.f) * m;
}

// ---------------- launch ----------------
extern "C" void kernel_launch(void* const* d_in, const int* in_sizes, int n_in,
                              void* d_out, int out_size)
{
    const float* times  = (const float*)d_in[0];
    const float* values = (const float*)d_in[1];
    const int*   meas   = (const int*)  d_in[2];
    const float* mask   = (const float*)d_in[3];
    const float* psi_w1 = (const float*)d_in[4];
    const float* psi_b1 = (const float*)d_in[5];
    const float* psi_w2 = (const float*)d_in[6];
    const float* psi_b2 = (const float*)d_in[7];
    const float* arho_w = (const float*)d_in[8];
    const float* arho_b = (const float*)d_in[9];
    const float* W_k    = (const float*)d_in[10];
    const float* W_q    = (const float*)d_in[11];
    const float* phi_w1 = (const float*)d_in[12];
    const float* phi_b1 = (const float*)d_in[13];
    const float* phi_w2 = (const float*)d_in[14];
    const float* phi_b2 = (const float*)d_in[15];
    const float* rho_w1 = (const float*)d_in[16];
    const float* rho_b1 = (const float*)d_in[17];
    const float* rho_w2 = (const float*)d_in[18];
    const float* rho_b2 = (const float*)d_in[19];
    float* out = (float*)d_out;

    k1_psi<<<NROWS/8, 256>>>(times, values, meas, mask, psi_w1, psi_b1, psi_w2, psi_b2);
    k2_cumsum<<<BB*32, 256>>>();
    k3_mid<<<NROWS/8, 256>>>(mask, arho_w, arho_b, W_k, W_q, phi_w1, phi_b1, phi_w2, phi_b2);
    k4_den<<<BB*4, 256>>>();
    k5_num<<<BB*4*32, 256>>>(mask);
    k6_rho<<<NROWS/8, 256>>>(mask, rho_w1, rho_b1, rho_w2, rho_b2, out);
}

// round 7
// speedup vs baseline: 2.0534x; 2.0534x over previous
#include <cuda_runtime.h>
#include <cuda_bf16.h>

#define BB 4
#define PP 2048
#define NROWS (BB*PP)

// ---------------- scratch (device globals; no allocation) ----------------
__device__ float g_combined[NROWS*32];    // raw combined features, row-major [row][32]
__device__ float g_encpsiT[BB*32*PP];     // psi output, feature-major [b][d][P]
__device__ float g_cumT   [BB*32*PP];     // cumsum, feature-major [b][d][P]
__device__ float g_encT   [BB*32*PP];     // phi output, feature-major [b][d][P]
__device__ float g_preattn[BB*4*PP];      // [b][h][P]
__device__ float g_agg2T  [BB*128*PP];    // out5, feature-major [b][h*32+d][P]

// ---------------- block scan helper ----------------
// Given each thread's local total, returns the exclusive prefix (carry) for
// that thread's chunk. Safe to call repeatedly (leading barrier protects ws8).
__device__ __forceinline__ float block_excl_from_tot(float tot, int tid, float* ws8)
{
    __syncthreads();
    float x = tot;
#pragma unroll
    for (int o = 1; o < 32; o <<= 1) {
        float y = __shfl_up_sync(0xffffffffu, x, o);
        if ((tid & 31) >= o) x += y;
    }
    if ((tid & 31) == 31) ws8[tid >> 5] = x;
    __syncthreads();
    float carry = 0.f;
    int w = tid >> 5;
    for (int i = 0; i < w; i++) carry += ws8[i];
    return carry + x - tot;
}

// ---------------- K1: combined features + psi MLP -> encpsiT ----------------
__global__ __launch_bounds__(256) void k1_psi(
    const float* __restrict__ times, const float* __restrict__ values,
    const int* __restrict__ meas, const float* __restrict__ mask,
    const float* __restrict__ w1, const float* __restrict__ b1,
    const float* __restrict__ w2, const float* __restrict__ b2)
{
    __shared__ float sw1[31*32], sb1[32], sw2[32*32], sb2[32];
    __shared__ float xb[8][32], hb[8][32];
    __shared__ float sbuf[8*36];          // [i][d] pad 36 -> conflict-free transpose
    int tid = threadIdx.x;
    for (int i = tid; i < 31*32; i += 256) sw1[i] = w1[i];
    for (int i = tid; i < 32*32; i += 256) sw2[i] = w2[i];
    if (tid < 32) { sb1[tid] = b1[tid]; sb2[tid] = b2[tid]; }
    __syncthreads();

    int warp = tid >> 5, lane = tid & 31;
    int row  = blockIdx.x * 8 + warp;
    int b = row >> 11;
    int p0 = (blockIdx.x * 8) & 2047;
    float m = mask[row];

    float c;
    if (lane < 8) {
        const float pv[8] = {1.f,1.f,10.f,10.f,100.f,100.f,1000.f,1000.f};
        float r = times[row] / pv[lane];
        c = ((lane & 1) == 0) ? sinf(r) : cosf(r);
    } else if (lane == 8) {
        c = values[row];
    } else if (lane <= 30) {
        c = (meas[row] == lane - 8) ? 1.f : 0.f;
    } else c = 0.f;

    g_combined[row*32 + lane] = c;
    xb[warp][lane] = c * m;
    __syncwarp();

    float acc = sb1[lane];
#pragma unroll
    for (int i = 0; i < 31; i++) acc = fmaf(xb[warp][i], sw1[i*32 + lane], acc);
    hb[warp][lane] = fmaxf(acc, 0.f) * m;
    __syncwarp();

    acc = sb2[lane];
#pragma unroll
    for (int i = 0; i < 32; i++) acc = fmaf(hb[warp][i], sw2[i*32 + lane], acc);
    sbuf[warp*36 + lane] = fmaxf(acc, 0.f) * m;
    __syncthreads();

    // transposed coalesced write: 8 consecutive p per d = 32B segments
    int d = tid >> 3, i = tid & 7;
    g_encpsiT[(b*32 + d)*PP + p0 + i] = sbuf[i*36 + d];
}

// ---------------- K2: cumsum along P per (b,d), fully coalesced ----------------
__global__ __launch_bounds__(256) void k2_cumsum()
{
    __shared__ float ws8[8];
    int id = blockIdx.x;              // 0..127 == b*32+d
    const float4* in4 = (const float4*)(g_encpsiT + id*PP);
    float4* out4 = (float4*)(g_cumT + id*PP);
    int t = threadIdx.x;

    float4 a = in4[t*2], bq = in4[t*2+1];
    float v[8] = {a.x,a.y,a.z,a.w,bq.x,bq.y,bq.z,bq.w};
#pragma unroll
    for (int i = 1; i < 8; i++) v[i] += v[i-1];
    float excl = block_excl_from_tot(v[7], t, ws8);
#pragma unroll
    for (int i = 0; i < 8; i++) v[i] += excl;
    out4[t*2]   = make_float4(v[0],v[1],v[2],v[3]);
    out4[t*2+1] = make_float4(v[4],v[5],v[6],v[7]);
}

// ---------------- K3: agg (arho), preattn (folded W_k@W_q), phi MLP -> encT ----------------
__global__ __launch_bounds__(256) void k3_mid(
    const float* __restrict__ mask,
    const float* __restrict__ arho_w, const float* __restrict__ arho_b,
    const float* __restrict__ W_k,    const float* __restrict__ W_q,
    const float* __restrict__ pw1, const float* __restrict__ pb1,
    const float* __restrict__ pw2, const float* __restrict__ pb2)
{
    __shared__ float sar[32*32], sarb[32];
    __shared__ float sWkq[4*63];
    __shared__ float sw1[31*32], sb1[32], sw2[32*32], sb2[32];
    __shared__ float c2[8][64], hb[8][32], xb[8][32];
    __shared__ float sc[8*36];        // cum tile [i][d]
    __shared__ float eb[8*36];        // enc out tile [i][d]
    int tid = threadIdx.x;
    for (int i = tid; i < 1024; i += 256) { sar[i] = arho_w[i]; sw2[i] = pw2[i]; }
    for (int i = tid; i < 992;  i += 256) sw1[i] = pw1[i];
    if (tid < 32) { sarb[tid] = arho_b[tid]; sb1[tid] = pb1[tid]; sb2[tid] = pb2[tid]; }
    // fold W_k @ W_q per head
    for (int j = tid; j < 252; j += 256) {
        int h = j / 63, i = j % 63;
        float a = 0.f;
#pragma unroll
        for (int dd = 0; dd < 16; dd++)
            a = fmaf(W_k[i*64 + dd*4 + h], W_q[h*16 + dd], a);
        sWkq[h*63 + i] = a;
    }

    int warp = tid >> 5, lane = tid & 31;
    int row = blockIdx.x * 8 + warp;
    int b = row >> 11, p = row & 2047;
    int p0 = (blockIdx.x * 8) & 2047;
    float m = mask[row];

    // load cum tile coalesced (32B segments), pre-apply 1/count and mask
    {
        int d = tid >> 3, i = tid & 7;
        float mm = mask[b*PP + p0 + i];
        sc[i*36 + d] = g_cumT[(b*32 + d)*PP + p0 + i] * (1.f/(float)(p0+i+1)) * mm;
    }

    float c = g_combined[row*32 + lane];
    c2[warp][lane] = c;
    xb[warp][lane] = (lane < 31) ? c * m : 0.f;
    __syncthreads();   // sc + weights ready

    float acc = sarb[lane];
#pragma unroll
    for (int i = 0; i < 32; i++) acc = fmaf(sc[warp*36 + i], sar[i*32 + lane], acc);
    c2[warp][31 + lane] = acc * m;
    __syncwarp();

    // preattn: 8 lanes per head
    int h = lane >> 3, ls = lane & 7;
    float pa = 0.f;
    for (int i = ls; i < 63; i += 8) pa = fmaf(c2[warp][i], sWkq[h*63 + i], pa);
    pa += __shfl_xor_sync(0xffffffffu, pa, 1);
    pa += __shfl_xor_sync(0xffffffffu, pa, 2);
    pa += __shfl_xor_sync(0xffffffffu, pa, 4);
    if (ls == 0) g_preattn[(b*4 + h)*PP + p] = pa * 0.25f * m * m;

    // phi MLP
    acc = sb1[lane];
#pragma unroll
    for (int i = 0; i < 31; i++) acc = fmaf(xb[warp][i], sw1[i*32 + lane], acc);
    float h1 = fmaxf(acc, 0.f) * m;
    hb[warp][lane] = h1;
    __syncwarp();
    acc = sb2[lane];
#pragma unroll
    for (int i = 0; i < 32; i++) acc = fmaf(hb[warp][i], sw2[i*32 + lane], acc);
    eb[warp*36 + lane] = fmaxf(acc, 0.f) * m;
    __syncthreads();

    int d = tid >> 3, i = tid & 7;
    g_encT[(b*32 + d)*PP + p0 + i] = eb[i*36 + d];
}

// ---------------- K45: fused softmax-denominator + 4 numerator scans ----------------
// grid 128: block = (b,h, d-group of 4). No max-subtraction needed: preattn is O(1)
// and the numerator/denominator ratio is invariant to the shift anyway.
__global__ __launch_bounds__(256) void k45_scan(const float* __restrict__ mask)
{
    __shared__ float ws8[8];
    int id = blockIdx.x;
    int bh = id >> 3, dg = id & 7;
    int b = bh >> 2, h = bh & 3;
    int t = threadIdx.x;

    const float4* a4 = (const float4*)(g_preattn + bh*PP);
    float4 A0 = a4[t*2], A1 = a4[t*2+1];
    float w[8];
    w[0]=__expf(A0.x); w[1]=__expf(A0.y); w[2]=__expf(A0.z); w[3]=__expf(A0.w);
    w[4]=__expf(A1.x); w[5]=__expf(A1.y); w[6]=__expf(A1.z); w[7]=__expf(A1.w);

    float s[8]; s[0]=w[0];
#pragma unroll
    for (int i = 1; i < 8; i++) s[i] = s[i-1] + w[i];
    float excl = block_excl_from_tot(s[7], t, ws8);
    float r[8];
#pragma unroll
    for (int i = 0; i < 8; i++) r[i] = 1.0f / (s[i] + excl);

    const float4* m4 = (const float4*)(mask + b*PP);
    float4 M0 = m4[t*2], M1 = m4[t*2+1];
    float mk[8] = {M0.x,M0.y,M0.z,M0.w,M1.x,M1.y,M1.z,M1.w};

#pragma unroll
    for (int j = 0; j < 4; j++) {
        int d = dg*4 + j;
        const float4* e4 = (const float4*)(g_encT + (b*32 + d)*PP);
        float4 E0 = e4[t*2], E1 = e4[t*2+1];
        float v[8] = {w[0]*E0.x, w[1]*E0.y, w[2]*E0.z, w[3]*E0.w,
                      w[4]*E1.x, w[5]*E1.y, w[6]*E1.z, w[7]*E1.w};
#pragma unroll
        for (int i = 1; i < 8; i++) v[i] += v[i-1];
        float ex2 = block_excl_from_tot(v[7], t, ws8);
        float o[8];
#pragma unroll
        for (int i = 0; i < 8; i++) o[i] = (v[i] + ex2) * r[i] * mk[i];
        float4* o4 = (float4*)(g_agg2T + ((b*128 + h*32 + d)*PP));
        o4[t*2]   = make_float4(o[0],o[1],o[2],o[3]);
        o4[t*2+1] = make_float4(o[4],o[5],o[6],o[7]);
    }
}

// ---------------- K6: rho MLP 128->64->64, coalesced tile from agg2T ----------------
__global__ __launch_bounds__(256) void k6_rho(
    const float* __restrict__ mask,
    const float* __restrict__ w1, const float* __restrict__ b1,
    const float* __restrict__ w2, const float* __restrict__ b2,
    float* __restrict__ out)
{
    __shared__ float sw1[128*64];     // 32 KB
    __shared__ float sw2[64*64];      // 16 KB
    __shared__ float sb1[64], sb2[64];
    __shared__ float tile[128*33];    // [f][pi], pad 33
    __shared__ float hbuf[32*65];     // [pi][hidden], pad 65
    __shared__ float mrow[32];
    int tid = threadIdx.x;
    for (int i = tid; i < 128*64; i += 256) sw1[i] = w1[i];
    for (int i = tid; i < 64*64;  i += 256) sw2[i] = w2[i];
    if (tid < 64) { sb1[tid] = b1[tid]; sb2[tid] = b2[tid]; }

    int r0 = blockIdx.x * 32;         // 32 rows per block, within one b
    int b = r0 >> 11, p0 = r0 & 2047;
    if (tid < 32) mrow[tid] = mask[r0 + tid];
    __syncthreads();                  // mrow + weights ready

    // coalesced tile load: per feature row f, 32 consecutive p (128B)
    for (int idx = tid; idx < 128*32; idx += 256) {
        int f = idx >> 5, pi = idx & 31;
        tile[f*33 + pi] = g_agg2T[(b*128 + f)*PP + p0 + pi] * mrow[pi];
    }
    __syncthreads();

    int warp = tid >> 5, lane = tid & 31;
    // each warp handles rows pi = warp*4 .. warp*4+3
    float a0[4], a1[4];
#pragma unroll
    for (int rr = 0; rr < 4; rr++) { a0[rr] = sb1[lane]; a1[rr] = sb1[lane+32]; }
#pragma unroll 4
    for (int f = 0; f < 128; f++) {
        float wv0 = sw1[f*64 + lane];
        float wv1 = sw1[f*64 + lane + 32];
#pragma unroll
        for (int rr = 0; rr < 4; rr++) {
            float xv = tile[f*33 + (warp*4 + rr)];
            a0[rr] = fmaf(xv, wv0, a0[rr]);
            a1[rr] = fmaf(xv, wv1, a1[rr]);
        }
    }
#pragma unroll
    for (int rr = 0; rr < 4; rr++) {
        int pi = warp*4 + rr;
        float m = mrow[pi];
        hbuf[pi*65 + lane]      = fmaxf(a0[rr], 0.f) * m;
        hbuf[pi*65 + lane + 32] = fmaxf(a1[rr], 0.f) * m;
    }
    __syncwarp();

#pragma unroll
    for (int rr = 0; rr < 4; rr++) { a0[rr] = sb2[lane]; a1[rr] = sb2[lane+32]; }
#pragma unroll 4
    for (int i = 0; i < 64; i++) {
        float wv0 = sw2[i*64 + lane];
        float wv1 = sw2[i*64 + lane + 32];
#pragma unroll
        for (int rr = 0; rr < 4; rr++) {
            float hv = hbuf[(warp*4 + rr)*65 + i];
            a0[rr] = fmaf(hv, wv0, a0[rr]);
            a1[rr] = fmaf(hv, wv1, a1[rr]);
        }
    }
#pragma unroll
    for (int rr = 0; rr < 4; rr++) {
        int pi = warp*4 + rr;
        float m = mrow[pi];
        int row = r0 + pi;
        out[row*64 + lane]      = fmaxf(a0[rr], 0.f) * m;
        out[row*64 + lane + 32] = fmaxf(a1[rr], 0.f) * m;
    }
}

// ---------------- launch ----------------
extern "C" void kernel_launch(void* const* d_in, const int* in_sizes, int n_in,
                              void* d_out, int out_size)
{
    const float* times  = (const float*)d_in[0];
    const float* values = (const float*)d_in[1];
    const int*   meas   = (const int*)  d_in[2];
    const float* mask   = (const float*)d_in[3];
    const float* psi_w1 = (const float*)d_in[4];
    const float* psi_b1 = (const float*)d_in[5];
    const float* psi_w2 = (const float*)d_in[6];
    const float* psi_b2 = (const float*)d_in[7];
    const float* arho_w = (const float*)d_in[8];
    const float* arho_b = (const float*)d_in[9];
    const float* W_k    = (const float*)d_in[10];
    const float* W_q    = (const float*)d_in[11];
    const float* phi_w1 = (const float*)d_in[12];
    const float* phi_b1 = (const float*)d_in[13];
    const float* phi_w2 = (const float*)d_in[14];
    const float* phi_b2 = (const float*)d_in[15];
    const float* rho_w1 = (const float*)d_in[16];
    const float* rho_b1 = (const float*)d_in[17];
    const float* rho_w2 = (const float*)d_in[18];
    const float* rho_b2 = (const float*)d_in[19];
    float* out = (float*)d_out;

    k1_psi  <<<NROWS/8, 256>>>(times, values, meas, mask, psi_w1, psi_b1, psi_w2, psi_b2);
    k2_cumsum<<<BB*32, 256>>>();
    k3_mid  <<<NROWS/8, 256>>>(mask, arho_w, arho_b, W_k, W_q, phi_w1, phi_b1, phi_w2, phi_b2);
    k45_scan<<<128, 256>>>(mask);
    k6_rho  <<<NROWS/32, 256>>>(mask, rho_w1, rho_b1, rho_w2, rho_b2, out);
}

// round 8
// speedup vs baseline: 2.1040x; 1.0246x over previous
#include <cuda_runtime.h>
#include <cuda_bf16.h>

#define BB 4
#define PP 2048
#define NROWS (BB*PP)
#define NB 128          // persistent grid size (<=148 SMs -> all resident)

// ---------------- scratch (device globals; no allocation) ----------------
__device__ float g_combined[NROWS*32];    // raw combined features, row-major [row][32]
__device__ float g_encpsiT[BB*32*PP];     // psi output, feature-major [b][d][P]
__device__ float g_cumT   [BB*32*PP];     // cumsum, feature-major [b][d][P]
__device__ float g_encT   [BB*32*PP];     // phi output, feature-major [b][d][P]
__device__ float g_preattn[BB*4*PP];      // [b][h][P]
__device__ float g_agg2T  [BB*128*PP];    // out5, feature-major [b][h*32+d][P]

// ---------------- software grid barrier (monotonic generation) ----------------
__device__ unsigned g_cnt[8];
__device__ unsigned g_gen[8];

__device__ __forceinline__ void grid_bar(int i)
{
    __syncthreads();
    if (threadIdx.x == 0) {
        __threadfence();
        unsigned gen = atomicAdd(&g_gen[i], 0u);
        unsigned a = atomicAdd(&g_cnt[i], 1u);
        if (a == NB - 1u) {
            g_cnt[i] = 0u;
            __threadfence();
            atomicAdd(&g_gen[i], 1u);
        } else {
            while (atomicAdd(&g_gen[i], 0u) == gen) { }
            __threadfence();
        }
    }
    __syncthreads();
}

// ---------------- block scan helper ----------------
__device__ __forceinline__ float block_excl_from_tot(float tot, int tid, float* ws8)
{
    __syncthreads();
    float x = tot;
#pragma unroll
    for (int o = 1; o < 32; o <<= 1) {
        float y = __shfl_up_sync(0xffffffffu, x, o);
        if ((tid & 31) >= o) x += y;
    }
    if ((tid & 31) == 31) ws8[tid >> 5] = x;
    __syncthreads();
    float carry = 0.f;
    int w = tid >> 5;
    for (int i = 0; i < w; i++) carry += ws8[i];
    return carry + x - tot;
}

// ---------------- fused persistent kernel ----------------
__global__ __launch_bounds__(256, 1) void fused_all(
    const float* __restrict__ times, const float* __restrict__ values,
    const int* __restrict__ meas, const float* __restrict__ mask,
    const float* __restrict__ psi_w1, const float* __restrict__ psi_b1,
    const float* __restrict__ psi_w2, const float* __restrict__ psi_b2,
    const float* __restrict__ arho_w, const float* __restrict__ arho_b,
    const float* __restrict__ W_k,    const float* __restrict__ W_q,
    const float* __restrict__ pw1, const float* __restrict__ pb1,
    const float* __restrict__ pw2, const float* __restrict__ pb2,
    const float* __restrict__ rw1, const float* __restrict__ rb1,
    const float* __restrict__ rw2, const float* __restrict__ rb2,
    float* __restrict__ out)
{
    __shared__ float s_ew1[128*64];   // rho w1 (32 KB)
    __shared__ float s_ew2[64*64];    // rho w2 (16 KB)
    __shared__ float s_eb1[64], s_eb2[64];
    __shared__ float S[6400];         // staged scratch union (25.6 KB)
    __shared__ float ws8[8];
    __shared__ float s_mrow[32];

    const int tid  = threadIdx.x;
    const int warp = tid >> 5, lane = tid & 31;

    // ============ Stage A: combined features + psi MLP -> encpsiT ============
    {
        float* sw1 = S;           // 992
        float* sw2 = S + 992;     // 1024
        float* sb1 = S + 2016;    // 32
        float* sb2 = S + 2048;    // 32
        float* xb  = S + 2080;    // 8*32
        float* hb  = S + 2336;    // 8*32
        float* sbuf= S + 2592;    // 8*36

        for (int i = tid; i < 992;  i += 256) sw1[i] = psi_w1[i];
        for (int i = tid; i < 1024; i += 256) sw2[i] = psi_w2[i];
        if (tid < 32) { sb1[tid] = psi_b1[tid]; sb2[tid] = psi_b2[tid]; }
        __syncthreads();

        for (int it = 0; it < 8; it++) {
            int vb  = blockIdx.x * 8 + it;
            int row = vb * 8 + warp;
            int b   = row >> 11;
            int p0  = (vb * 8) & 2047;
            float m = mask[row];

            float c;
            if (lane < 8) {
                const float pv[8] = {1.f,1.f,10.f,10.f,100.f,100.f,1000.f,1000.f};
                float r = times[row] / pv[lane];
                c = ((lane & 1) == 0) ? sinf(r) : cosf(r);
            } else if (lane == 8) {
                c = values[row];
            } else if (lane <= 30) {
                c = (meas[row] == lane - 8) ? 1.f : 0.f;
            } else c = 0.f;

            g_combined[row*32 + lane] = c;
            xb[warp*32 + lane] = c * m;
            __syncwarp();

            float acc = sb1[lane];
#pragma unroll
            for (int i = 0; i < 31; i++) acc = fmaf(xb[warp*32 + i], sw1[i*32 + lane], acc);
            hb[warp*32 + lane] = fmaxf(acc, 0.f) * m;
            __syncwarp();

            acc = sb2[lane];
#pragma unroll
            for (int i = 0; i < 32; i++) acc = fmaf(hb[warp*32 + i], sw2[i*32 + lane], acc);
            sbuf[warp*36 + lane] = fmaxf(acc, 0.f) * m;
            __syncthreads();

            int d = tid >> 3, ii = tid & 7;
            g_encpsiT[(b*32 + d)*PP + p0 + ii] = sbuf[ii*36 + d];
            __syncthreads();
        }
    }
    grid_bar(0);

    // ---- prefetch stage-C weights + rho weights into smem (overlaps stage B) ----
    {
        float* sar  = S;          // 1024
        float* sw1  = S + 1024;   // 992
        float* sw2  = S + 2016;   // 1024
        float* sWkq = S + 3040;   // 252
        float* sarb = S + 3292;   // 32
        float* sb1  = S + 3324;   // 32
        float* sb2  = S + 3356;   // 32
        for (int i = tid; i < 1024; i += 256) { sar[i] = arho_w[i]; sw2[i] = pw2[i]; }
        for (int i = tid; i < 992;  i += 256) sw1[i] = pw1[i];
        if (tid < 32) { sarb[tid] = arho_b[tid]; sb1[tid] = pb1[tid]; sb2[tid] = pb2[tid]; }
        for (int j = tid; j < 252; j += 256) {     // fold W_k @ W_q per head
            int h = j / 63, i = j % 63;
            float a = 0.f;
#pragma unroll
            for (int dd = 0; dd < 16; dd++)
                a = fmaf(W_k[i*64 + dd*4 + h], W_q[h*16 + dd], a);
            sWkq[h*63 + i] = a;
        }
        for (int i = tid; i < 128*64; i += 256) s_ew1[i] = rw1[i];
        for (int i = tid; i < 64*64;  i += 256) s_ew2[i] = rw2[i];
        if (tid < 64) { s_eb1[tid] = rb1[tid]; s_eb2[tid] = rb2[tid]; }
    }

    // ============ Stage B: cumsum along P per (b,d) ============
    {
        int id = blockIdx.x;              // b*32+d
        const float4* in4 = (const float4*)(g_encpsiT + id*PP);
        float4* out4 = (float4*)(g_cumT + id*PP);

        float4 a = in4[tid*2], bq = in4[tid*2+1];
        float v[8] = {a.x,a.y,a.z,a.w,bq.x,bq.y,bq.z,bq.w};
#pragma unroll
        for (int i = 1; i < 8; i++) v[i] += v[i-1];
        float excl = block_excl_from_tot(v[7], tid, ws8);
#pragma unroll
        for (int i = 0; i < 8; i++) v[i] += excl;
        out4[tid*2]   = make_float4(v[0],v[1],v[2],v[3]);
        out4[tid*2+1] = make_float4(v[4],v[5],v[6],v[7]);
    }
    grid_bar(1);

    // ============ Stage C: arho + preattn + phi MLP -> encT ============
    {
        float* sar  = S;
        float* sw1  = S + 1024;
        float* sw2  = S + 2016;
        float* sWkq = S + 3040;
        float* sarb = S + 3292;
        float* sb1  = S + 3324;
        float* sb2  = S + 3356;
        float* c2   = S + 3392;   // 8*64
        float* hb   = S + 3904;   // 8*32
        float* xb   = S + 4160;   // 8*32
        float* sc   = S + 4416;   // 8*36
        float* eb   = S + 4704;   // 8*36

        for (int it = 0; it < 8; it++) {
            int vb  = blockIdx.x * 8 + it;
            int row = vb * 8 + warp;
            int b   = row >> 11, p = row & 2047;
            int p0  = (vb * 8) & 2047;
            float m = mask[row];

            {   // cum tile, coalesced; pre-apply 1/count and mask
                int d = tid >> 3, ii = tid & 7;
                float mm = mask[b*PP + p0 + ii];
                sc[ii*36 + d] = g_cumT[(b*32 + d)*PP + p0 + ii] * (1.f/(float)(p0+ii+1)) * mm;
            }
            float c = g_combined[row*32 + lane];
            c2[warp*64 + lane] = c;
            xb[warp*32 + lane] = (lane < 31) ? c * m : 0.f;
            __syncthreads();

            float acc = sarb[lane];
#pragma unroll
            for (int i = 0; i < 32; i++) acc = fmaf(sc[warp*36 + i], sar[i*32 + lane], acc);
            c2[warp*64 + 31 + lane] = acc * m;
            __syncwarp();

            int h = lane >> 3, ls = lane & 7;
            float pa = 0.f;
            for (int i = ls; i < 63; i += 8) pa = fmaf(c2[warp*64 + i], sWkq[h*63 + i], pa);
            pa += __shfl_xor_sync(0xffffffffu, pa, 1);
            pa += __shfl_xor_sync(0xffffffffu, pa, 2);
            pa += __shfl_xor_sync(0xffffffffu, pa, 4);
            if (ls == 0) g_preattn[(b*4 + h)*PP + p] = pa * 0.25f * m * m;

            acc = sb1[lane];
#pragma unroll
            for (int i = 0; i < 31; i++) acc = fmaf(xb[warp*32 + i], sw1[i*32 + lane], acc);
            float h1 = fmaxf(acc, 0.f) * m;
            hb[warp*32 + lane] = h1;
            __syncwarp();
            acc = sb2[lane];
#pragma unroll
            for (int i = 0; i < 32; i++) acc = fmaf(hb[warp*32 + i], sw2[i*32 + lane], acc);
            eb[warp*36 + lane] = fmaxf(acc, 0.f) * m;
            __syncthreads();

            int d = tid >> 3, ii = tid & 7;
            g_encT[(b*32 + d)*PP + p0 + ii] = eb[ii*36 + d];
            __syncthreads();
        }
    }
    grid_bar(2);

    // ============ Stage D: softmax-denominator + 4 numerator scans ============
    {
        int id = blockIdx.x;
        int bh = id >> 3, dg = id & 7;
        int b = bh >> 2, h = bh & 3;

        const float4* a4 = (const float4*)(g_preattn + bh*PP);
        float4 A0 = a4[tid*2], A1 = a4[tid*2+1];
        float w[8];
        w[0]=__expf(A0.x); w[1]=__expf(A0.y); w[2]=__expf(A0.z); w[3]=__expf(A0.w);
        w[4]=__expf(A1.x); w[5]=__expf(A1.y); w[6]=__expf(A1.z); w[7]=__expf(A1.w);

        float s[8]; s[0]=w[0];
#pragma unroll
        for (int i = 1; i < 8; i++) s[i] = s[i-1] + w[i];
        float excl = block_excl_from_tot(s[7], tid, ws8);
        float r[8];
#pragma unroll
        for (int i = 0; i < 8; i++) r[i] = 1.0f / (s[i] + excl);

        const float4* m4 = (const float4*)(mask + b*PP);
        float4 M0 = m4[tid*2], M1 = m4[tid*2+1];
        float mk[8] = {M0.x,M0.y,M0.z,M0.w,M1.x,M1.y,M1.z,M1.w};

#pragma unroll
        for (int j = 0; j < 4; j++) {
            int d = dg*4 + j;
            const float4* e4 = (const float4*)(g_encT + (b*32 + d)*PP);
            float4 E0 = e4[tid*2], E1 = e4[tid*2+1];
            float v[8] = {w[0]*E0.x, w[1]*E0.y, w[2]*E0.z, w[3]*E0.w,
                          w[4]*E1.x, w[5]*E1.y, w[6]*E1.z, w[7]*E1.w};
#pragma unroll
            for (int i = 1; i < 8; i++) v[i] += v[i-1];
            float ex2 = block_excl_from_tot(v[7], tid, ws8);
            float o[8];
#pragma unroll
            for (int i = 0; i < 8; i++) o[i] = (v[i] + ex2) * r[i] * mk[i];
            float4* o4 = (float4*)(g_agg2T + ((b*128 + h*32 + d)*PP));
            o4[tid*2]   = make_float4(o[0],o[1],o[2],o[3]);
            o4[tid*2+1] = make_float4(o[4],o[5],o[6],o[7]);
        }
    }
    grid_bar(3);

    // ============ Stage E: rho MLP 128->64->64 ============
    {
        float* tile = S;          // 128*33 = 4224
        float* hbuf = S + 4224;   // 32*65 = 2080

        for (int it = 0; it < 2; it++) {
            int r0 = (blockIdx.x * 2 + it) * 32;
            int b = r0 >> 11, p0 = r0 & 2047;
            if (tid < 32) s_mrow[tid] = mask[r0 + tid];
            __syncthreads();

            for (int idx = tid; idx < 128*32; idx += 256) {
                int f = idx >> 5, pi = idx & 31;
                tile[f*33 + pi] = g_agg2T[(b*128 + f)*PP + p0 + pi] * s_mrow[pi];
            }
            __syncthreads();

            float a0[4], a1[4];
#pragma unroll
            for (int rr = 0; rr < 4; rr++) { a0[rr] = s_eb1[lane]; a1[rr] = s_eb1[lane+32]; }
#pragma unroll 4
            for (int f = 0; f < 128; f++) {
                float wv0 = s_ew1[f*64 + lane];
                float wv1 = s_ew1[f*64 + lane + 32];
#pragma unroll
                for (int rr = 0; rr < 4; rr++) {
                    float xv = tile[f*33 + (warp*4 + rr)];
                    a0[rr] = fmaf(xv, wv0, a0[rr]);
                    a1[rr] = fmaf(xv, wv1, a1[rr]);
                }
            }
#pragma unroll
            for (int rr = 0; rr < 4; rr++) {
                int pi = warp*4 + rr;
                float m = s_mrow[pi];
                hbuf[pi*65 + lane]      = fmaxf(a0[rr], 0.f) * m;
                hbuf[pi*65 + lane + 32] = fmaxf(a1[rr], 0.f) * m;
            }
            __syncwarp();

#pragma unroll
            for (int rr = 0; rr < 4; rr++) { a0[rr] = s_eb2[lane]; a1[rr] = s_eb2[lane+32]; }
#pragma unroll 4
            for (int i = 0; i < 64; i++) {
                float wv0 = s_ew2[i*64 + lane];
                float wv1 = s_ew2[i*64 + lane + 32];
#pragma unroll
                for (int rr = 0; rr < 4; rr++) {
                    float hv = hbuf[(warp*4 + rr)*65 + i];
                    a0[rr] = fmaf(hv, wv0, a0[rr]);
                    a1[rr] = fmaf(hv, wv1, a1[rr]);
                }
            }
#pragma unroll
            for (int rr = 0; rr < 4; rr++) {
                int pi = warp*4 + rr;
                float m = s_mrow[pi];
                int row = r0 + pi;
                out[row*64 + lane]      = fmaxf(a0[rr], 0.f) * m;
                out[row*64 + lane + 32] = fmaxf(a1[rr], 0.f) * m;
            }
            __syncthreads();
        }
    }
}

// ---------------- launch ----------------
extern "C" void kernel_launch(void* const* d_in, const int* in_sizes, int n_in,
                              void* d_out, int out_size)
{
    const float* times  = (const float*)d_in[0];
    const float* values = (const float*)d_in[1];
    const int*   meas   = (const int*)  d_in[2];
    const float* mask   = (const float*)d_in[3];
    const float* psi_w1 = (const float*)d_in[4];
    const float* psi_b1 = (const float*)d_in[5];
    const float* psi_w2 = (const float*)d_in[6];
    const float* psi_b2 = (const float*)d_in[7];
    const float* arho_w = (const float*)d_in[8];
    const float* arho_b = (const float*)d_in[9];
    const float* W_k    = (const float*)d_in[10];
    const float* W_q    = (const float*)d_in[11];
    const float* phi_w1 = (const float*)d_in[12];
    const float* phi_b1 = (const float*)d_in[13];
    const float* phi_w2 = (const float*)d_in[14];
    const float* phi_b2 = (const float*)d_in[15];
    const float* rho_w1 = (const float*)d_in[16];
    const float* rho_b1 = (const float*)d_in[17];
    const float* rho_w2 = (const float*)d_in[18];
    const float* rho_b2 = (const float*)d_in[19];
    float* out = (float*)d_out;

    fused_all<<<NB, 256>>>(times, values, meas, mask,
                           psi_w1, psi_b1, psi_w2, psi_b2,
                           arho_w, arho_b, W_k, W_q,
                           phi_w1, phi_b1, phi_w2, phi_b2,
                           rho_w1, rho_b1, rho_w2, rho_b2, out);
}

// round 9
// speedup vs baseline: 2.3670x; 1.1250x over previous
#include <cuda_runtime.h>
#include <cuda_bf16.h>

#define BB 4
#define PP 2048
#define NROWS (BB*PP)
#define NB 128          // persistent grid size (<=148 SMs -> all resident)
#define NT 512          // threads per block (16 warps -> 4 per SMSP)

// ---------------- scratch (device globals; no allocation) ----------------
__device__ float g_combined[NROWS*32];    // raw combined features, row-major [row][32]
__device__ float g_encpsiT[BB*32*PP];     // psi output, feature-major [b][d][P]
__device__ float g_cumT   [BB*32*PP];     // cumsum, feature-major [b][d][P]
__device__ float g_encT   [BB*32*PP];     // phi output, feature-major [b][d][P]
__device__ float g_preattn[BB*4*PP];      // [b][h][P]
__device__ float g_agg2T  [BB*128*PP];    // out5, feature-major [b][h*32+d][P]

// ---------------- software grid barrier (monotonic generation) ----------------
__device__ unsigned g_cnt[8];
__device__ unsigned g_gen[8];

__device__ __forceinline__ void grid_bar(int i)
{
    __syncthreads();
    if (threadIdx.x == 0) {
        __threadfence();
        unsigned gen = *(volatile unsigned*)&g_gen[i];
        unsigned a = atomicAdd(&g_cnt[i], 1u);
        if (a == NB - 1u) {
            g_cnt[i] = 0u;
            __threadfence();
            atomicAdd(&g_gen[i], 1u);
        } else {
            while (*(volatile unsigned*)&g_gen[i] == gen) { }
            __threadfence();
        }
    }
    __syncthreads();
}

// ---------------- block scan helper (16 warps) ----------------
// Returns exclusive prefix of per-thread totals. Leading barrier protects ws16 reuse.
__device__ __forceinline__ float block_excl_from_tot(float tot, int tid, float* ws16)
{
    __syncthreads();
    float x = tot;
#pragma unroll
    for (int o = 1; o < 32; o <<= 1) {
        float y = __shfl_up_sync(0xffffffffu, x, o);
        if ((tid & 31) >= o) x += y;
    }
    if ((tid & 31) == 31) ws16[tid >> 5] = x;
    __syncthreads();
    float carry = 0.f;
    int w = tid >> 5;
    for (int i = 0; i < w; i++) carry += ws16[i];
    return carry + x - tot;
}

// ---------------- fused persistent kernel ----------------
__global__ __launch_bounds__(NT, 1) void fused_all(
    const float* __restrict__ times, const float* __restrict__ values,
    const int* __restrict__ meas, const float* __restrict__ mask,
    const float* __restrict__ psi_w1, const float* __restrict__ psi_b1,
    const float* __restrict__ psi_w2, const float* __restrict__ psi_b2,
    const float* __restrict__ arho_w, const float* __restrict__ arho_b,
    const float* __restrict__ W_k,    const float* __restrict__ W_q,
    const float* __restrict__ pw1, const float* __restrict__ pb1,
    const float* __restrict__ pw2, const float* __restrict__ pb2,
    const float* __restrict__ rw1, const float* __restrict__ rb1,
    const float* __restrict__ rw2, const float* __restrict__ rb2,
    float* __restrict__ out)
{
    __shared__ float s_ew1[128*64];   // rho w1 (32 KB)
    __shared__ float s_ew2[64*64];    // rho w2 (16 KB)
    __shared__ float s_eb1[64], s_eb2[64];
    __shared__ float S[6600];         // staged scratch union (26.4 KB)
    __shared__ float ws16[16];
    __shared__ float s_mrow[32];

    const int tid  = threadIdx.x;
    const int warp = tid >> 5, lane = tid & 31;

    // ============ Stage A: combined features + psi MLP -> encpsiT ============
    {
        float* sw1 = S;           // 992
        float* sw2 = S + 992;     // 1024
        float* sb1 = S + 2016;    // 32
        float* sb2 = S + 2048;    // 32
        float* xb  = S + 2080;    // 16*32
        float* hb  = S + 2592;    // 16*32
        float* sbuf= S + 3104;    // 16*36

        for (int i = tid; i < 992;  i += NT) sw1[i] = psi_w1[i];
        for (int i = tid; i < 1024; i += NT) sw2[i] = psi_w2[i];
        if (tid < 32) { sb1[tid] = psi_b1[tid]; sb2[tid] = psi_b2[tid]; }
        __syncthreads();

        for (int it = 0; it < 4; it++) {
            int vb  = blockIdx.x * 4 + it;
            int row = vb * 16 + warp;
            int b   = row >> 11;
            int p0  = (vb * 16) & 2047;
            float m = mask[row];

            float c;
            if (lane < 8) {
                const float pv[8] = {1.f,1.f,10.f,10.f,100.f,100.f,1000.f,1000.f};
                float r = times[row] / pv[lane];
                c = ((lane & 1) == 0) ? sinf(r) : cosf(r);
            } else if (lane == 8) {
                c = values[row];
            } else if (lane <= 30) {
                c = (meas[row] == lane - 8) ? 1.f : 0.f;
            } else c = 0.f;

            g_combined[row*32 + lane] = c;
            xb[warp*32 + lane] = c * m;
            __syncwarp();

            float acc = sb1[lane];
#pragma unroll
            for (int i = 0; i < 31; i++) acc = fmaf(xb[warp*32 + i], sw1[i*32 + lane], acc);
            hb[warp*32 + lane] = fmaxf(acc, 0.f) * m;
            __syncwarp();

            acc = sb2[lane];
#pragma unroll
            for (int i = 0; i < 32; i++) acc = fmaf(hb[warp*32 + i], sw2[i*32 + lane], acc);
            sbuf[warp*36 + lane] = fmaxf(acc, 0.f) * m;
            __syncthreads();

            // transposed coalesced write: 16 consecutive p per d (64B)
            int d = tid >> 4, ii = tid & 15;
            g_encpsiT[(b*32 + d)*PP + p0 + ii] = sbuf[ii*36 + d];
            __syncthreads();
        }
    }
    grid_bar(0);

    // ---- prefetch stage-C weights + rho weights into smem (overlaps stage B) ----
    {
        float* sar  = S;          // 1024
        float* sw1  = S + 1024;   // 992
        float* sw2  = S + 2016;   // 1024
        float* sWkq = S + 3040;   // 252
        float* sarb = S + 3292;   // 32
        float* sb1  = S + 3324;   // 32
        float* sb2  = S + 3356;   // 32
        for (int i = tid; i < 1024; i += NT) { sar[i] = arho_w[i]; sw2[i] = pw2[i]; }
        for (int i = tid; i < 992;  i += NT) sw1[i] = pw1[i];
        if (tid < 32) { sarb[tid] = arho_b[tid]; sb1[tid] = pb1[tid]; sb2[tid] = pb2[tid]; }
        for (int j = tid; j < 252; j += NT) {     // fold W_k @ W_q per head
            int h = j / 63, i = j % 63;
            float a = 0.f;
#pragma unroll
            for (int dd = 0; dd < 16; dd++)
                a = fmaf(W_k[i*64 + dd*4 + h], W_q[h*16 + dd], a);
            sWkq[h*63 + i] = a;
        }
        for (int i = tid; i < 128*64; i += NT) s_ew1[i] = rw1[i];
        for (int i = tid; i < 64*64;  i += NT) s_ew2[i] = rw2[i];
        if (tid < 64) { s_eb1[tid] = rb1[tid]; s_eb2[tid] = rb2[tid]; }
    }

    // ============ Stage B: cumsum along P per (b,d) ============
    {
        int id = blockIdx.x;              // b*32+d
        const float4* in4 = (const float4*)(g_encpsiT + id*PP);
        float4* out4 = (float4*)(g_cumT + id*PP);

        float4 a = in4[tid];
        float v[4] = {a.x, a.y, a.z, a.w};
#pragma unroll
        for (int i = 1; i < 4; i++) v[i] += v[i-1];
        float excl = block_excl_from_tot(v[3], tid, ws16);
#pragma unroll
        for (int i = 0; i < 4; i++) v[i] += excl;
        out4[tid] = make_float4(v[0], v[1], v[2], v[3]);
    }
    grid_bar(1);

    // ============ Stage C: arho + preattn + phi MLP -> encT ============
    {
        float* sar  = S;
        float* sw1  = S + 1024;
        float* sw2  = S + 2016;
        float* sWkq = S + 3040;
        float* sarb = S + 3292;
        float* sb1  = S + 3324;
        float* sb2  = S + 3356;
        float* c2   = S + 3392;   // 16*64 = 1024
        float* hb   = S + 4416;   // 16*32
        float* xb   = S + 4928;   // 16*32
        float* sc   = S + 5440;   // 16*36
        float* eb   = S + 6016;   // 16*36

        for (int it = 0; it < 4; it++) {
            int vb  = blockIdx.x * 4 + it;
            int row = vb * 16 + warp;
            int b   = row >> 11, p = row & 2047;
            int p0  = (vb * 16) & 2047;
            float m = mask[row];

            {   // cum tile, coalesced; pre-apply 1/count and mask
                int d = tid >> 4, ii = tid & 15;
                float mm = mask[b*PP + p0 + ii];
                sc[ii*36 + d] = g_cumT[(b*32 + d)*PP + p0 + ii] * (1.f/(float)(p0+ii+1)) * mm;
            }
            float c = g_combined[row*32 + lane];
            c2[warp*64 + lane] = c;
            xb[warp*32 + lane] = (lane < 31) ? c * m : 0.f;
            __syncthreads();

            float acc = sarb[lane];
#pragma unroll
            for (int i = 0; i < 32; i++) acc = fmaf(sc[warp*36 + i], sar[i*32 + lane], acc);
            c2[warp*64 + 31 + lane] = acc * m;
            __syncwarp();

            int h = lane >> 3, ls = lane & 7;
            float pa = 0.f;
            for (int i = ls; i < 63; i += 8) pa = fmaf(c2[warp*64 + i], sWkq[h*63 + i], pa);
            pa += __shfl_xor_sync(0xffffffffu, pa, 1);
            pa += __shfl_xor_sync(0xffffffffu, pa, 2);
            pa += __shfl_xor_sync(0xffffffffu, pa, 4);
            if (ls == 0) g_preattn[(b*4 + h)*PP + p] = pa * 0.25f * m * m;

            acc = sb1[lane];
#pragma unroll
            for (int i = 0; i < 31; i++) acc = fmaf(xb[warp*32 + i], sw1[i*32 + lane], acc);
            float h1 = fmaxf(acc, 0.f) * m;
            hb[warp*32 + lane] = h1;
            __syncwarp();
            acc = sb2[lane];
#pragma unroll
            for (int i = 0; i < 32; i++) acc = fmaf(hb[warp*32 + i], sw2[i*32 + lane], acc);
            eb[warp*36 + lane] = fmaxf(acc, 0.f) * m;
            __syncthreads();

            int d = tid >> 4, ii = tid & 15;
            g_encT[(b*32 + d)*PP + p0 + ii] = eb[ii*36 + d];
            __syncthreads();
        }
    }
    grid_bar(2);

    // ============ Stage D: softmax-denominator + 4 numerator scans ============
    // No max-subtraction needed: the num/den ratio is shift-invariant and
    // preattn is O(1) (validated rel_err ~3e-7).
    {
        int id = blockIdx.x;
        int bh = id >> 3, dg = id & 7;
        int b = bh >> 2, h = bh & 3;

        const float4* a4 = (const float4*)(g_preattn + bh*PP);
        float4 A0 = a4[tid];
        float w[4];
        w[0]=__expf(A0.x); w[1]=__expf(A0.y); w[2]=__expf(A0.z); w[3]=__expf(A0.w);

        float s[4]; s[0]=w[0];
#pragma unroll
        for (int i = 1; i < 4; i++) s[i] = s[i-1] + w[i];
        float excl = block_excl_from_tot(s[3], tid, ws16);
        float r[4];
#pragma unroll
        for (int i = 0; i < 4; i++) r[i] = 1.0f / (s[i] + excl);

        const float4* m4 = (const float4*)(mask + b*PP);
        float4 M0 = m4[tid];
        float mk[4] = {M0.x, M0.y, M0.z, M0.w};

#pragma unroll
        for (int j = 0; j < 4; j++) {
            int d = dg*4 + j;
            const float4* e4 = (const float4*)(g_encT + (b*32 + d)*PP);
            float4 E0 = e4[tid];
            float v[4] = {w[0]*E0.x, w[1]*E0.y, w[2]*E0.z, w[3]*E0.w};
#pragma unroll
            for (int i = 1; i < 4; i++) v[i] += v[i-1];
            float ex2 = block_excl_from_tot(v[3], tid, ws16);
            float o[4];
#pragma unroll
            for (int i = 0; i < 4; i++) o[i] = (v[i] + ex2) * r[i] * mk[i];
            float4* o4 = (float4*)(g_agg2T + ((b*128 + h*32 + d)*PP));
            o4[tid] = make_float4(o[0], o[1], o[2], o[3]);
        }
    }
    grid_bar(3);

    // ============ Stage E: rho MLP 128->64->64 ============
    {
        float* tile = S;          // 128*33 = 4224
        float* hbuf = S + 4224;   // 32*65 = 2080

        for (int it = 0; it < 2; it++) {
            int r0 = (blockIdx.x * 2 + it) * 32;
            int b = r0 >> 11, p0 = r0 & 2047;
            if (tid < 32) s_mrow[tid] = mask[r0 + tid];
            __syncthreads();

            for (int idx = tid; idx < 128*32; idx += NT) {
                int f = idx >> 5, pi = idx & 31;
                tile[f*33 + pi] = g_agg2T[(b*128 + f)*PP + p0 + pi] * s_mrow[pi];
            }
            __syncthreads();

            // 16 warps x 2 rows each
            float a0[2], a1[2];
#pragma unroll
            for (int rr = 0; rr < 2; rr++) { a0[rr] = s_eb1[lane]; a1[rr] = s_eb1[lane+32]; }
#pragma unroll 8
            for (int f = 0; f < 128; f++) {
                float wv0 = s_ew1[f*64 + lane];
                float wv1 = s_ew1[f*64 + lane + 32];
#pragma unroll
                for (int rr = 0; rr < 2; rr++) {
                    float xv = tile[f*33 + (warp*2 + rr)];
                    a0[rr] = fmaf(xv, wv0, a0[rr]);
                    a1[rr] = fmaf(xv, wv1, a1[rr]);
                }
            }
#pragma unroll
            for (int rr = 0; rr < 2; rr++) {
                int pi = warp*2 + rr;
                float m = s_mrow[pi];
                hbuf[pi*65 + lane]      = fmaxf(a0[rr], 0.f) * m;
                hbuf[pi*65 + lane + 32] = fmaxf(a1[rr], 0.f) * m;
            }
            __syncwarp();

#pragma unroll
            for (int rr = 0; rr < 2; rr++) { a0[rr] = s_eb2[lane]; a1[rr] = s_eb2[lane+32]; }
#pragma unroll 8
            for (int i = 0; i < 64; i++) {
                float wv0 = s_ew2[i*64 + lane];
                float wv1 = s_ew2[i*64 + lane + 32];
#pragma unroll
                for (int rr = 0; rr < 2; rr++) {
                    float hv = hbuf[(warp*2 + rr)*65 + i];
                    a0[rr] = fmaf(hv, wv0, a0[rr]);
                    a1[rr] = fmaf(hv, wv1, a1[rr]);
                }
            }
#pragma unroll
            for (int rr = 0; rr < 2; rr++) {
                int pi = warp*2 + rr;
                float m = s_mrow[pi];
                int row = r0 + pi;
                out[row*64 + lane]      = fmaxf(a0[rr], 0.f) * m;
                out[row*64 + lane + 32] = fmaxf(a1[rr], 0.f) * m;
            }
            __syncthreads();
        }
    }
}

// ---------------- launch ----------------
extern "C" void kernel_launch(void* const* d_in, const int* in_sizes, int n_in,
                              void* d_out, int out_size)
{
    const float* times  = (const float*)d_in[0];
    const float* values = (const float*)d_in[1];
    const int*   meas   = (const int*)  d_in[2];
    const float* mask   = (const float*)d_in[3];
    const float* psi_w1 = (const float*)d_in[4];
    const float* psi_b1 = (const float*)d_in[5];
    const float* psi_w2 = (const float*)d_in[6];
    const float* psi_b2 = (const float*)d_in[7];
    const float* arho_w = (const float*)d_in[8];
    const float* arho_b = (const float*)d_in[9];
    const float* W_k    = (const float*)d_in[10];
    const float* W_q    = (const float*)d_in[11];
    const float* phi_w1 = (const float*)d_in[12];
    const float* phi_b1 = (const float*)d_in[13];
    const float* phi_w2 = (const float*)d_in[14];
    const float* phi_b2 = (const float*)d_in[15];
    const float* rho_w1 = (const float*)d_in[16];
    const float* rho_b1 = (const float*)d_in[17];
    const float* rho_w2 = (const float*)d_in[18];
    const float* rho_b2 = (const float*)d_in[19];
    float* out = (float*)d_out;

    fused_all<<<NB, NT>>>(times, values, meas, mask,
                          psi_w1, psi_b1, psi_w2, psi_b2,
                          arho_w, arho_b, W_k, W_q,
                          phi_w1, phi_b1, phi_w2, phi_b2,
                          rho_w1, rho_b1, rho_w2, rho_b2, out);
}